// round 15
// baseline (speedup 1.0000x reference)
#include <cuda_runtime.h>
#include <float.h>

#define EPS 1e-5f
#define NEG 0.2f

typedef unsigned long long ull;

__device__ __forceinline__ ull fma2(ull a, ull b, ull c) {
    ull d; asm("fma.rn.f32x2 %0, %1, %2, %3;" : "=l"(d) : "l"(a), "l"(b), "l"(c)); return d;
}
__device__ __forceinline__ ull add2(ull a, ull b) {
    ull d; asm("add.rn.f32x2 %0, %1, %2;" : "=l"(d) : "l"(a), "l"(b)); return d;
}
__device__ __forceinline__ ull mul2(ull a, ull b) {
    ull d; asm("mul.rn.f32x2 %0, %1, %2;" : "=l"(d) : "l"(a), "l"(b)); return d;
}
__device__ __forceinline__ ull pk(float lo, float hi) {
    ull r; asm("mov.b64 %0, {%1, %2};" : "=l"(r) : "f"(lo), "f"(hi)); return r;
}
__device__ __forceinline__ ull dup(float v) { return pk(v, v); }
__device__ __forceinline__ void unpk(ull v, float& lo, float& hi) {
    asm("mov.b64 {%0, %1}, %2;" : "=f"(lo), "=f"(hi) : "l"(v));
}
// lrelu(v) = 0.6*v + 0.4*|v|  (== v for v>0, 0.2v for v<0)
__device__ __forceinline__ ull lrelu2(ull v) {
    ull av = v & 0x7FFFFFFF7FFFFFFFULL;
    return fma2(dup(0.4f), av, mul2(dup(0.6f), v));
}

// BN-folded weights + pre-transposed float4 weight tables
__device__ float g_wt[64 * 6], g_bt[64];
__device__ float g_wp1[64 * 3], g_bp1[64];
__device__ float g_wg1[16 * 6], g_bg1[16];
__device__ float g_wa1[16 * 6], g_ba1[16];
__device__ float4 g_w2q[64 * 16];    // [j][cg] -> (W2[cg][j], W2[cg+16][j], W2[cg+32][j], W2[cg+48][j])
__device__ float4 g_wa2q[16 * 16];   // [j][cg]
__device__ float4 g_wtq[6 * 16];     // [i][cg] (folded trans weights)

__global__ void fold_kernel(
    const float* __restrict__ trans_w, const float* __restrict__ trans_g,
    const float* __restrict__ trans_b, const float* __restrict__ trans_m,
    const float* __restrict__ trans_v,
    const float* __restrict__ pos_w1, const float* __restrict__ pos_g,
    const float* __restrict__ pos_b, const float* __restrict__ pos_m,
    const float* __restrict__ pos_v,
    const float* __restrict__ gate_w1, const float* __restrict__ gate_g,
    const float* __restrict__ gate_b, const float* __restrict__ gate_m,
    const float* __restrict__ gate_v,
    const float* __restrict__ attn_w1, const float* __restrict__ attn_g,
    const float* __restrict__ attn_b, const float* __restrict__ attn_m,
    const float* __restrict__ attn_v,
    const float* __restrict__ pos_w2, const float* __restrict__ attn_w2)
{
    int i = threadIdx.x;
    if (i < 64) {
        float s = trans_g[i] * rsqrtf(trans_v[i] + EPS);
        #pragma unroll
        for (int j = 0; j < 6; j++) g_wt[i * 6 + j] = trans_w[i * 6 + j] * s;
        g_bt[i] = trans_b[i] - trans_m[i] * s;
        float sp = pos_g[i] * rsqrtf(pos_v[i] + EPS);
        #pragma unroll
        for (int j = 0; j < 3; j++) g_wp1[i * 3 + j] = pos_w1[i * 3 + j] * sp;
        g_bp1[i] = pos_b[i] - pos_m[i] * sp;
    }
    if (i < 16) {
        float sg = gate_g[i] * rsqrtf(gate_v[i] + EPS);
        #pragma unroll
        for (int j = 0; j < 6; j++) g_wg1[i * 6 + j] = gate_w1[i * 6 + j] * sg;
        g_bg1[i] = gate_b[i] - gate_m[i] * sg;
        float sa = attn_g[i] * rsqrtf(attn_v[i] + EPS);
        #pragma unroll
        for (int j = 0; j < 6; j++) g_wa1[i * 6 + j] = attn_w1[i * 6 + j] * sa;
        g_ba1[i] = attn_b[i] - attn_m[i] * sa;
    }
    __syncthreads();
    // one-time transposed float4 tables (cost irrelevant: single block)
    for (int idx = i; idx < 1024; idx += 128) {
        int j = idx >> 4, cgi = idx & 15;
        g_w2q[idx] = make_float4(pos_w2[cgi * 64 + j],
                                 pos_w2[(cgi + 16) * 64 + j],
                                 pos_w2[(cgi + 32) * 64 + j],
                                 pos_w2[(cgi + 48) * 64 + j]);
    }
    for (int idx = i; idx < 256; idx += 128) {
        int j = idx >> 4, cgi = idx & 15;
        g_wa2q[idx] = make_float4(attn_w2[cgi * 16 + j],
                                  attn_w2[(cgi + 16) * 16 + j],
                                  attn_w2[(cgi + 32) * 16 + j],
                                  attn_w2[(cgi + 48) * 16 + j]);
    }
    if (i < 96) {
        int ii = i >> 4, cgi = i & 15;
        g_wtq[i] = make_float4(g_wt[cgi * 6 + ii],
                               g_wt[(cgi + 16) * 6 + ii],
                               g_wt[(cgi + 32) * 6 + ii],
                               g_wt[(cgi + 48) * 6 + ii]);
    }
}

// Block = 128 threads = 4 n-positions (one warp each). Phase 2 lane mapping:
// lane = (cg = lane>>1, kg = lane&1): each lane owns 4 channels
// {cg, cg+16, cg+32, cg+48} over its 10-k half (kg). Weights fetched as one
// LDS.128 per j from tables pre-transposed in fold_kernel (coalesced staging).
__global__ __launch_bounds__(128, 4) void gsl_main_kernel(
    const float* __restrict__ x,
    const float* __restrict__ pos_b2,
    const float* __restrict__ gate_w2, const float* __restrict__ gate_b2,
    const float* __restrict__ attn_b2,
    float* __restrict__ out)
{
    __shared__ __align__(16) float ph[4 * 64 * 20];   // [g][j][k]
    __shared__ __align__(16) float ah[4 * 16 * 20];   // [g][j][k]
    __shared__ __align__(16) float xsh[4 * 6 * 20];   // [g][ch][k]
    __shared__ __align__(16) float gm[4 * 20];        // [g][k]
    __shared__ __align__(16) float4 w2q[64 * 16];     // [j][cg]
    __shared__ __align__(16) float4 wa2q[16 * 16];    // [j][cg]
    __shared__ __align__(16) float4 wtq[6 * 16];      // [i][cg]
    __shared__ float outsh[64 * 6];                   // [c][g] padded stride 6

    const int tid = threadIdx.x;
    const int b = blockIdx.x >> 11;
    const int n0 = (blockIdx.x & 2047) << 2;

    // ---- cooperative loads: x tile + coalesced float4 weight copies ----
    const float* xb = x + ((size_t)b * 6 * 8192 + n0) * 20;
    for (int idx = tid; idx < 480; idx += 128) {
        int ch = idx / 80; int r = idx - ch * 80;          // r = g*20 + k
        xsh[(r / 20) * 120 + ch * 20 + (r % 20)] = xb[(size_t)ch * 8192 * 20 + r];
    }
    for (int idx = tid; idx < 1024; idx += 128) w2q[idx] = g_w2q[idx];
    for (int idx = tid; idx < 256; idx += 128) wa2q[idx] = g_wa2q[idx];
    if (tid < 96) wtq[tid] = g_wtq[tid];
    __syncthreads();

    const int g = tid >> 5;
    const int lane = tid & 31;
    float* phg = ph + g * 1280;
    float* ahg = ah + g * 320;
    const float* xg = xsh + g * 120;

    // ---- phase 1 (warp-local): pos_h rows (lane, lane+32) ----
    {
        const ull* x3 = reinterpret_cast<const ull*>(xg + 60);
        #pragma unroll
        for (int rr = 0; rr < 2; rr++) {
            int j = lane + rr * 32;
            ull w0 = dup(g_wp1[j * 3 + 0]);
            ull w1 = dup(g_wp1[j * 3 + 1]);
            ull w2d = dup(g_wp1[j * 3 + 2]);
            ull bb = dup(g_bp1[j]);
            ull* dst = reinterpret_cast<ull*>(phg) + j * 10;
            #pragma unroll
            for (int q = 0; q < 10; q++) {
                ull v = fma2(w0, x3[q], bb);
                v = fma2(w1, x3[10 + q], v);
                v = fma2(w2d, x3[20 + q], v);
                dst[q] = lrelu2(v);
            }
        }
    }
    // ---- attn_h rows (lanes 0..15) ----
    if (lane < 16) {
        const ull* xrow = reinterpret_cast<const ull*>(xg);
        ull bb = dup(g_ba1[lane]);
        ull acc[10];
        #pragma unroll
        for (int q = 0; q < 10; q++) acc[q] = bb;
        #pragma unroll
        for (int i = 0; i < 6; i++) {
            ull wd = dup(g_wa1[lane * 6 + i]);
            #pragma unroll
            for (int q = 0; q < 10; q++) acc[q] = fma2(wd, xrow[i * 10 + q], acc[q]);
        }
        ull* dst = reinterpret_cast<ull*>(ahg) + lane * 10;
        #pragma unroll
        for (int q = 0; q < 10; q++) dst[q] = lrelu2(acc[q]);
    }
    // ---- gate_map (lanes 0..19) ----
    if (lane < 20) {
        float acc = gate_b2[0];
        #pragma unroll
        for (int j = 0; j < 16; j++) {
            float v = g_bg1[j];
            #pragma unroll
            for (int i = 0; i < 6; i++) v += g_wg1[j * 6 + i] * xg[i * 20 + lane];
            v = v > 0.f ? v : NEG * v;
            acc += gate_w2[j] * v;
        }
        gm[g * 20 + lane] = 1.f / (1.f + __expf(-acc));
    }
    __syncwarp();

    // ---- phase 2: (cg, kg) mapping ----
    const int kg = lane & 1;          // k-half: 10 k = 5 ulls
    const int cg = lane >> 1;         // channel group: channels cg + 16m
    const int koff = kg * 10;         // float offset of this lane's k-half

    // (a) pos_enc accumulators pe[m][p]
    ull pe[4][5];
    #pragma unroll
    for (int m = 0; m < 4; m++) {
        ull bv = dup(pos_b2[cg + 16 * m]);
        #pragma unroll
        for (int p = 0; p < 5; p++) pe[m][p] = bv;
    }
    #pragma unroll 4
    for (int j = 0; j < 64; ++j) {
        const ull* row = reinterpret_cast<const ull*>(phg + j * 20 + koff);
        float4 wv = w2q[j * 16 + cg];
        ull w0 = dup(wv.x), w1 = dup(wv.y), w2v = dup(wv.z), w3 = dup(wv.w);
        #pragma unroll
        for (int p = 0; p < 5; p++) {
            ull r = row[p];
            pe[0][p] = fma2(w0, r, pe[0][p]);
            pe[1][p] = fma2(w1, r, pe[1][p]);
            pe[2][p] = fma2(w2v, r, pe[2][p]);
            pe[3][p] = fma2(w3, r, pe[3][p]);
        }
    }

    // (b) trans conv, folded: tf = lrelu(trans) + pe
    ull tf[4][5];
    #pragma unroll
    for (int m = 0; m < 4; m++) {
        ull bv = dup(g_bt[cg + 16 * m]);
        #pragma unroll
        for (int p = 0; p < 5; p++) tf[m][p] = bv;
    }
    #pragma unroll
    for (int i = 0; i < 6; i++) {
        const ull* row = reinterpret_cast<const ull*>(xg + i * 20 + koff);
        float4 wv = wtq[i * 16 + cg];
        ull w0 = dup(wv.x), w1 = dup(wv.y), w2v = dup(wv.z), w3 = dup(wv.w);
        #pragma unroll
        for (int p = 0; p < 5; p++) {
            ull r = row[p];
            tf[0][p] = fma2(w0, r, tf[0][p]);
            tf[1][p] = fma2(w1, r, tf[1][p]);
            tf[2][p] = fma2(w2v, r, tf[2][p]);
            tf[3][p] = fma2(w3, r, tf[3][p]);
        }
    }
    #pragma unroll
    for (int m = 0; m < 4; m++)
        #pragma unroll
        for (int p = 0; p < 5; p++)
            tf[m][p] = add2(lrelu2(tf[m][p]), pe[m][p]);

    // (c) attn logits: init from pe + bias (pe dead after), then matmul
    ull al[4][5];
    #pragma unroll
    for (int m = 0; m < 4; m++) {
        ull bv = dup(attn_b2[cg + 16 * m]);
        #pragma unroll
        for (int p = 0; p < 5; p++) al[m][p] = add2(pe[m][p], bv);
    }
    #pragma unroll 4
    for (int j = 0; j < 16; ++j) {
        const ull* row = reinterpret_cast<const ull*>(ahg + j * 20 + koff);
        float4 wv = wa2q[j * 16 + cg];
        ull w0 = dup(wv.x), w1 = dup(wv.y), w2v = dup(wv.z), w3 = dup(wv.w);
        #pragma unroll
        for (int p = 0; p < 5; p++) {
            ull r = row[p];
            al[0][p] = fma2(w0, r, al[0][p]);
            al[1][p] = fma2(w1, r, al[1][p]);
            al[2][p] = fma2(w2v, r, al[2][p]);
            al[3][p] = fma2(w3, r, al[3][p]);
        }
    }

    // (d+e) per-channel softmax + gated max, combining k-halves via shfl_xor(1)
    {
        ull gk[5];
        {
            const ull* gmr = reinterpret_cast<const ull*>(gm + g * 20 + koff);
            #pragma unroll
            for (int p = 0; p < 5; p++) gk[p] = gmr[p];
        }
        float outv[4];
        #pragma unroll
        for (int m = 0; m < 4; m++) {
            float a, bq;
            float mloc = -FLT_MAX;
            #pragma unroll
            for (int p = 0; p < 5; p++) {
                unpk(al[m][p], a, bq);
                mloc = fmaxf(mloc, fmaxf(a, bq));
            }
            float mm = fmaxf(mloc, __shfl_xor_sync(0xffffffffu, mloc, 1));
            ull se2 = dup(0.f), sa2 = dup(0.f);
            float mxloc = -FLT_MAX;
            #pragma unroll
            for (int p = 0; p < 5; p++) {
                unpk(al[m][p], a, bq);
                ull e = pk(__expf(a - mm), __expf(bq - mm));
                se2 = add2(se2, e);
                sa2 = fma2(tf[m][p], e, sa2);
                unpk(mul2(tf[m][p], gk[p]), a, bq);
                mxloc = fmaxf(mxloc, fmaxf(a, bq));
            }
            float s, t;
            unpk(se2, s, t); float seloc = s + t;
            unpk(sa2, s, t); float saloc = s + t;
            float setot = seloc + __shfl_xor_sync(0xffffffffu, seloc, 1);
            float satot = saloc + __shfl_xor_sync(0xffffffffu, saloc, 1);
            float mxtot = fmaxf(mxloc, __shfl_xor_sync(0xffffffffu, mxloc, 1));
            outv[m] = satot / setot + mxtot;
        }
        if (kg == 0) {
            #pragma unroll
            for (int m = 0; m < 4; m++) outsh[(cg + 16 * m) * 6 + g] = outv[m];
        }
    }
    __syncthreads();

    // coalesced-ish output: 64 ch x 4 n as float2 stores
    {
        int c = tid >> 1, h = (tid & 1) * 2;
        float2 v = make_float2(outsh[c * 6 + h], outsh[c * 6 + h + 1]);
        *reinterpret_cast<float2*>(out + ((size_t)b * 64 + c) * 8192 + n0 + h) = v;
    }
}

extern "C" void kernel_launch(void* const* d_in, const int* in_sizes, int n_in,
                              void* d_out, int out_size)
{
    (void)in_sizes; (void)n_in; (void)out_size;
    const float* x = (const float*)d_in[0];

    fold_kernel<<<1, 128>>>(
        (const float*)d_in[1], (const float*)d_in[2], (const float*)d_in[3],
        (const float*)d_in[4], (const float*)d_in[5],
        (const float*)d_in[6], (const float*)d_in[7], (const float*)d_in[8],
        (const float*)d_in[9], (const float*)d_in[10],
        (const float*)d_in[13], (const float*)d_in[14], (const float*)d_in[15],
        (const float*)d_in[16], (const float*)d_in[17],
        (const float*)d_in[20], (const float*)d_in[21], (const float*)d_in[22],
        (const float*)d_in[23], (const float*)d_in[24],
        (const float*)d_in[11], (const float*)d_in[25]);   // pos_w2, attn_w2

    gsl_main_kernel<<<16384, 128>>>(
        x,
        (const float*)d_in[12],                            // pos_b2
        (const float*)d_in[18], (const float*)d_in[19],    // gate_w2, gate_b2
        (const float*)d_in[26],                            // attn_b2
        (float*)d_out);
}

// round 16
// speedup vs baseline: 1.5504x; 1.5504x over previous
#include <cuda_runtime.h>
#include <float.h>

#define EPS 1e-5f
#define NEG 0.2f

typedef unsigned long long ull;

__device__ __forceinline__ ull fma2(ull a, ull b, ull c) {
    ull d; asm("fma.rn.f32x2 %0, %1, %2, %3;" : "=l"(d) : "l"(a), "l"(b), "l"(c)); return d;
}
__device__ __forceinline__ ull add2(ull a, ull b) {
    ull d; asm("add.rn.f32x2 %0, %1, %2;" : "=l"(d) : "l"(a), "l"(b)); return d;
}
__device__ __forceinline__ ull mul2(ull a, ull b) {
    ull d; asm("mul.rn.f32x2 %0, %1, %2;" : "=l"(d) : "l"(a), "l"(b)); return d;
}
__device__ __forceinline__ ull pk(float lo, float hi) {
    ull r; asm("mov.b64 %0, {%1, %2};" : "=l"(r) : "f"(lo), "f"(hi)); return r;
}
__device__ __forceinline__ ull dup(float v) { return pk(v, v); }
__device__ __forceinline__ void unpk(ull v, float& lo, float& hi) {
    asm("mov.b64 {%0, %1}, %2;" : "=f"(lo), "=f"(hi) : "l"(v));
}
// lrelu(v) = 0.6*v + 0.4*|v|  (== v for v>0, 0.2v for v<0)
__device__ __forceinline__ ull lrelu2(ull v) {
    ull av = v & 0x7FFFFFFF7FFFFFFFULL;
    return fma2(dup(0.4f), av, mul2(dup(0.6f), v));
}

// BN-folded weights (setup kernel writes, main kernel reads)
__device__ float g_wt[64 * 6], g_bt[64];
__device__ float g_wp1[64 * 3], g_bp1[64];
__device__ float g_wg1[16 * 6], g_bg1[16];
__device__ float g_wa1[16 * 6], g_ba1[16];

__global__ void fold_kernel(
    const float* __restrict__ trans_w, const float* __restrict__ trans_g,
    const float* __restrict__ trans_b, const float* __restrict__ trans_m,
    const float* __restrict__ trans_v,
    const float* __restrict__ pos_w1, const float* __restrict__ pos_g,
    const float* __restrict__ pos_b, const float* __restrict__ pos_m,
    const float* __restrict__ pos_v,
    const float* __restrict__ gate_w1, const float* __restrict__ gate_g,
    const float* __restrict__ gate_b, const float* __restrict__ gate_m,
    const float* __restrict__ gate_v,
    const float* __restrict__ attn_w1, const float* __restrict__ attn_g,
    const float* __restrict__ attn_b, const float* __restrict__ attn_m,
    const float* __restrict__ attn_v)
{
    int i = threadIdx.x;
    if (i < 64) {
        float s = trans_g[i] * rsqrtf(trans_v[i] + EPS);
        #pragma unroll
        for (int j = 0; j < 6; j++) g_wt[i * 6 + j] = trans_w[i * 6 + j] * s;
        g_bt[i] = trans_b[i] - trans_m[i] * s;
        float sp = pos_g[i] * rsqrtf(pos_v[i] + EPS);
        #pragma unroll
        for (int j = 0; j < 3; j++) g_wp1[i * 3 + j] = pos_w1[i * 3 + j] * sp;
        g_bp1[i] = pos_b[i] - pos_m[i] * sp;
    }
    if (i < 16) {
        float sg = gate_g[i] * rsqrtf(gate_v[i] + EPS);
        #pragma unroll
        for (int j = 0; j < 6; j++) g_wg1[i * 6 + j] = gate_w1[i * 6 + j] * sg;
        g_bg1[i] = gate_b[i] - gate_m[i] * sg;
        float sa = attn_g[i] * rsqrtf(attn_v[i] + EPS);
        #pragma unroll
        for (int j = 0; j < 6; j++) g_wa1[i * 6 + j] = attn_w1[i * 6 + j] * sa;
        g_ba1[i] = attn_b[i] - attn_m[i] * sa;
    }
}

// Block = 128 threads = 4 n-positions (one warp each); each lane owns channels
// (lane, lane+32). k-dim (20) packed as 10 f32x2 pairs; shared rows read as
// float4. Phase-2 stages ordered (pe -> tfull -> al) so at most two 40-reg
// accumulator sets are ever live: fits 128 regs -> 4 CTAs/SM, no spills.
__global__ __launch_bounds__(128, 4) void gsl_main_kernel(
    const float* __restrict__ x,
    const float* __restrict__ pos_w2, const float* __restrict__ pos_b2,
    const float* __restrict__ gate_w2, const float* __restrict__ gate_b2,
    const float* __restrict__ attn_w2, const float* __restrict__ attn_b2,
    float* __restrict__ out)
{
    __shared__ __align__(16) float ph[4 * 64 * 20];   // [g][j][k]
    __shared__ __align__(16) float ah[4 * 16 * 20];   // [g][j][k]
    __shared__ __align__(16) float xsh[4 * 6 * 20];   // [g][ch][k]
    __shared__ __align__(16) float gm[4 * 20];        // [g][k]
    __shared__ float w2sh[64 * 65];                   // [j][c] padded
    __shared__ float wa2sh[16 * 65];                  // [j][c] padded
    __shared__ float outsh[64 * 6];                   // [c][g] padded stride 6

    const int tid = threadIdx.x;
    const int b = blockIdx.x >> 11;
    const int n0 = (blockIdx.x & 2047) << 2;

    // ---- cooperative loads: x tile + transposed weights ----
    const float* xb = x + ((size_t)b * 6 * 8192 + n0) * 20;
    for (int idx = tid; idx < 480; idx += 128) {
        int ch = idx / 80; int r = idx - ch * 80;          // r = g*20 + k
        xsh[(r / 20) * 120 + ch * 20 + (r % 20)] = xb[(size_t)ch * 8192 * 20 + r];
    }
    for (int idx = tid; idx < 4096; idx += 128) {
        int c = idx >> 6, j = idx & 63;
        w2sh[j * 65 + c] = pos_w2[idx];
    }
    for (int idx = tid; idx < 1024; idx += 128) {
        int c = idx >> 4, j = idx & 15;
        wa2sh[j * 65 + c] = attn_w2[idx];
    }
    __syncthreads();

    const int g = tid >> 5;
    const int lane = tid & 31;
    float* phg = ph + g * 1280;
    float* ahg = ah + g * 320;
    const float* xg = xsh + g * 120;

    // ---- phase 1 (warp-local): pos_h rows (lane, lane+32) ----
    {
        const ull* x3 = reinterpret_cast<const ull*>(xg + 60);
        #pragma unroll
        for (int rr = 0; rr < 2; rr++) {
            int j = lane + rr * 32;
            ull w0 = dup(g_wp1[j * 3 + 0]);
            ull w1 = dup(g_wp1[j * 3 + 1]);
            ull w2d = dup(g_wp1[j * 3 + 2]);
            ull bb = dup(g_bp1[j]);
            ull* dst = reinterpret_cast<ull*>(phg) + j * 10;
            #pragma unroll
            for (int q = 0; q < 10; q++) {
                ull v = fma2(w0, x3[q], bb);
                v = fma2(w1, x3[10 + q], v);
                v = fma2(w2d, x3[20 + q], v);
                dst[q] = lrelu2(v);
            }
        }
    }
    // ---- attn_h rows (lanes 0..15) ----
    if (lane < 16) {
        const ull* xrow = reinterpret_cast<const ull*>(xg);
        ull bb = dup(g_ba1[lane]);
        ull acc[10];
        #pragma unroll
        for (int q = 0; q < 10; q++) acc[q] = bb;
        #pragma unroll
        for (int i = 0; i < 6; i++) {
            ull wd = dup(g_wa1[lane * 6 + i]);
            #pragma unroll
            for (int q = 0; q < 10; q++) acc[q] = fma2(wd, xrow[i * 10 + q], acc[q]);
        }
        ull* dst = reinterpret_cast<ull*>(ahg) + lane * 10;
        #pragma unroll
        for (int q = 0; q < 10; q++) dst[q] = lrelu2(acc[q]);
    }
    // ---- gate_map (lanes 0..19) ----
    if (lane < 20) {
        float acc = gate_b2[0];
        #pragma unroll
        for (int j = 0; j < 16; j++) {
            float v = g_bg1[j];
            #pragma unroll
            for (int i = 0; i < 6; i++) v += g_wg1[j * 6 + i] * xg[i * 20 + lane];
            v = v > 0.f ? v : NEG * v;
            acc += gate_w2[j] * v;
        }
        gm[g * 20 + lane] = 1.f / (1.f + __expf(-acc));
    }
    __syncwarp();

    // ---- phase 2 ----
    const int c0 = lane, c1 = lane + 32;

    // (a) pos_enc accumulators
    ull pe0[10], pe1[10];
    {
        ull B0 = dup(pos_b2[c0]), B1 = dup(pos_b2[c1]);
        #pragma unroll
        for (int kp = 0; kp < 10; kp++) { pe0[kp] = B0; pe1[kp] = B1; }
    }
    #pragma unroll 2
    for (int jc = 0; jc < 8; ++jc) {
        ull w0[8], w1[8];
        #pragma unroll
        for (int t = 0; t < 8; t++) {
            int j = jc * 8 + t;
            w0[t] = dup(w2sh[j * 65 + c0]);
            w1[t] = dup(w2sh[j * 65 + c1]);
        }
        #pragma unroll
        for (int t = 0; t < 8; t++) {
            const float4* row = reinterpret_cast<const float4*>(phg + (jc * 8 + t) * 20);
            #pragma unroll
            for (int q = 0; q < 5; q++) {
                float4 p = row[q];
                ull plo = pk(p.x, p.y), phi = pk(p.z, p.w);
                pe0[2 * q]     = fma2(w0[t], plo, pe0[2 * q]);
                pe0[2 * q + 1] = fma2(w0[t], phi, pe0[2 * q + 1]);
                pe1[2 * q]     = fma2(w1[t], plo, pe1[2 * q]);
                pe1[2 * q + 1] = fma2(w1[t], phi, pe1[2 * q + 1]);
            }
        }
    }

    // (b) trans conv, folded immediately: tfull = lrelu(trans) + pos_enc
    ull tf0[10], tf1[10];
    {
        ull B0 = dup(g_bt[c0]), B1 = dup(g_bt[c1]);
        #pragma unroll
        for (int kp = 0; kp < 10; kp++) { tf0[kp] = B0; tf1[kp] = B1; }
        #pragma unroll
        for (int i = 0; i < 6; i++) {
            ull wt0 = dup(g_wt[c0 * 6 + i]), wt1 = dup(g_wt[c1 * 6 + i]);
            const float4* row = reinterpret_cast<const float4*>(xg + i * 20);
            #pragma unroll
            for (int q = 0; q < 5; q++) {
                float4 p = row[q];
                ull plo = pk(p.x, p.y), phi = pk(p.z, p.w);
                tf0[2 * q]     = fma2(wt0, plo, tf0[2 * q]);
                tf0[2 * q + 1] = fma2(wt0, phi, tf0[2 * q + 1]);
                tf1[2 * q]     = fma2(wt1, plo, tf1[2 * q]);
                tf1[2 * q + 1] = fma2(wt1, phi, tf1[2 * q + 1]);
            }
        }
        #pragma unroll
        for (int kp = 0; kp < 10; kp++) {
            tf0[kp] = add2(lrelu2(tf0[kp]), pe0[kp]);
            tf1[kp] = add2(lrelu2(tf1[kp]), pe1[kp]);
        }
    }

    // (c) attn logits init consumes pe (pe dead after this)
    ull al0[10], al1[10];
    {
        ull B0 = dup(attn_b2[c0]), B1 = dup(attn_b2[c1]);
        #pragma unroll
        for (int kp = 0; kp < 10; kp++) {
            al0[kp] = add2(pe0[kp], B0);
            al1[kp] = add2(pe1[kp], B1);
        }
    }
    #pragma unroll 2
    for (int jc = 0; jc < 2; ++jc) {
        ull w0[8], w1[8];
        #pragma unroll
        for (int t = 0; t < 8; t++) {
            int j = jc * 8 + t;
            w0[t] = dup(wa2sh[j * 65 + c0]);
            w1[t] = dup(wa2sh[j * 65 + c1]);
        }
        #pragma unroll
        for (int t = 0; t < 8; t++) {
            const float4* row = reinterpret_cast<const float4*>(ahg + (jc * 8 + t) * 20);
            #pragma unroll
            for (int q = 0; q < 5; q++) {
                float4 p = row[q];
                ull plo = pk(p.x, p.y), phi = pk(p.z, p.w);
                al0[2 * q]     = fma2(w0[t], plo, al0[2 * q]);
                al0[2 * q + 1] = fma2(w0[t], phi, al0[2 * q + 1]);
                al1[2 * q]     = fma2(w1[t], plo, al1[2 * q]);
                al1[2 * q + 1] = fma2(w1[t], phi, al1[2 * q + 1]);
            }
        }
    }

    // (d) softmax: scalar max-reduce, exp in place, packed sum
    ull se0, se1;
    {
        float m0 = -FLT_MAX, m1 = -FLT_MAX;
        #pragma unroll
        for (int kp = 0; kp < 10; kp++) {
            float a, bq;
            unpk(al0[kp], a, bq); m0 = fmaxf(m0, fmaxf(a, bq));
            unpk(al1[kp], a, bq); m1 = fmaxf(m1, fmaxf(a, bq));
        }
        se0 = dup(0.f); se1 = dup(0.f);
        #pragma unroll
        for (int kp = 0; kp < 10; kp++) {
            float a, bq;
            unpk(al0[kp], a, bq);
            al0[kp] = pk(__expf(a - m0), __expf(bq - m0));
            se0 = add2(se0, al0[kp]);
            unpk(al1[kp], a, bq);
            al1[kp] = pk(__expf(a - m1), __expf(bq - m1));
            se1 = add2(se1, al1[kp]);
        }
    }

    // (e) epilogue: sa += tfull*e; mx = max(tfull*gm)
    {
        ull sa0 = dup(0.f), sa1 = dup(0.f);
        float mx0 = -FLT_MAX, mx1 = -FLT_MAX;
        const ull* gmr = reinterpret_cast<const ull*>(gm + g * 20);
        #pragma unroll
        for (int kp = 0; kp < 10; kp++) {
            ull gk = gmr[kp];
            float a, bq;
            sa0 = fma2(tf0[kp], al0[kp], sa0);
            unpk(mul2(tf0[kp], gk), a, bq);
            mx0 = fmaxf(mx0, fmaxf(a, bq));
            sa1 = fma2(tf1[kp], al1[kp], sa1);
            unpk(mul2(tf1[kp], gk), a, bq);
            mx1 = fmaxf(mx1, fmaxf(a, bq));
        }
        float a, bq, s, t;
        unpk(sa0, a, bq); unpk(se0, s, t);
        outsh[c0 * 6 + g] = (a + bq) / (s + t) + mx0;
        unpk(sa1, a, bq); unpk(se1, s, t);
        outsh[c1 * 6 + g] = (a + bq) / (s + t) + mx1;
    }
    __syncthreads();

    // coalesced-ish output: 64 ch x 4 n as float2 stores
    {
        int c = tid >> 1, h = (tid & 1) * 2;
        float2 v = make_float2(outsh[c * 6 + h], outsh[c * 6 + h + 1]);
        *reinterpret_cast<float2*>(out + ((size_t)b * 64 + c) * 8192 + n0 + h) = v;
    }
}

extern "C" void kernel_launch(void* const* d_in, const int* in_sizes, int n_in,
                              void* d_out, int out_size)
{
    (void)in_sizes; (void)n_in; (void)out_size;
    const float* x = (const float*)d_in[0];

    fold_kernel<<<1, 64>>>(
        (const float*)d_in[1], (const float*)d_in[2], (const float*)d_in[3],
        (const float*)d_in[4], (const float*)d_in[5],
        (const float*)d_in[6], (const float*)d_in[7], (const float*)d_in[8],
        (const float*)d_in[9], (const float*)d_in[10],
        (const float*)d_in[13], (const float*)d_in[14], (const float*)d_in[15],
        (const float*)d_in[16], (const float*)d_in[17],
        (const float*)d_in[20], (const float*)d_in[21], (const float*)d_in[22],
        (const float*)d_in[23], (const float*)d_in[24]);

    gsl_main_kernel<<<16384, 128>>>(
        x,
        (const float*)d_in[11], (const float*)d_in[12],   // pos_w2, pos_b2
        (const float*)d_in[18], (const float*)d_in[19],   // gate_w2, gate_b2
        (const float*)d_in[25], (const float*)d_in[26],   // attn_w2, attn_b2
        (float*)d_out);
}